// round 13
// baseline (speedup 1.0000x reference)
#include <cuda_runtime.h>
#include <cuda_fp16.h>
#include <cstdint>
#include <stdint.h>
#include <math.h>

// ---------------------------------------------------------------------------
// MemoryBankContrastLoss — JAX-threefry-exact pipeline, mma.sync (HMMA) GEMM.
// u==0 -> main, u==1 -> ema.  6-launch pipeline.
// ---------------------------------------------------------------------------

#define NCLS 20
#define MEMB 512
#define MV   256
#define DIM  256
#define NANC 5120    // 20*256 anchors
#define NSEL 10240   // 20*512 selections per modality
#define PTOT 65536   // pixels per modality
#define NTIL 40      // 5120/128 col tiles per GEMM dimension

// ------------------------------ scratch ------------------------------------
__device__ unsigned       g_mask[2][PTOT / 32];
__device__ unsigned short g_msel[2][PTOT];
__device__ unsigned short g_manc[2][PTOT];
__device__ int    g_pinv  [2][NCLS][MEMB];
__device__ int    g_samp  [2][NCLS][MV];
__device__ float  g_selvec[2][NSEL][DIM];
__device__ float  g_anch  [NANC][DIM];
__device__ float  g_con   [2][NANC][DIM];
__device__ float  g_psum  [2][NCLS][DIM];
__device__ float  g_part  [2][NTIL][NANC];
__device__ double g_loss;
__device__ unsigned g_done;

// fp16 copies for the tensor-core GEMM
__device__ __align__(16) __half g_A16[NANC*DIM];
__device__ __align__(16) __half g_B16[2][NANC*DIM];

// ------------------------------ threefry -----------------------------------
__host__ __device__ __forceinline__ void tf2x32(unsigned k0, unsigned k1,
                                                unsigned c0, unsigned c1,
                                                unsigned& o0, unsigned& o1) {
    unsigned ks0 = k0, ks1 = k1, ks2 = k0 ^ k1 ^ 0x1BD11BDAu;
    unsigned x0 = c0 + ks0, x1 = c1 + ks1;
#define TFRND(r) { x0 += x1; x1 = (x1 << r) | (x1 >> (32 - r)); x1 ^= x0; }
    TFRND(13) TFRND(15) TFRND(26) TFRND(6)   x0 += ks1; x1 += ks2 + 1u;
    TFRND(17) TFRND(29) TFRND(16) TFRND(24)  x0 += ks2; x1 += ks0 + 2u;
    TFRND(13) TFRND(15) TFRND(26) TFRND(6)   x0 += ks0; x1 += ks1 + 3u;
    TFRND(17) TFRND(29) TFRND(16) TFRND(24)  x0 += ks1; x1 += ks2 + 4u;
    TFRND(13) TFRND(15) TFRND(26) TFRND(6)   x0 += ks2; x1 += ks0 + 5u;
#undef TFRND
    o0 = x0; o1 = x1;
}

__host__ __device__ __forceinline__ unsigned tfx(unsigned k0, unsigned k1, unsigned ctr) {
    unsigned a, b;
    tf2x32(k0, k1, 0u, ctr, a, b);
    return a ^ b;
}

// ------------------------------ helpers ------------------------------------
__device__ __forceinline__ float wred(float v) {
#pragma unroll
    for (int o = 16; o > 0; o >>= 1) v += __shfl_xor_sync(0xffffffffu, v, o);
    return v;
}

__device__ __forceinline__ void bitonic(unsigned long long* a, int n, int tid, int nt) {
    for (int size = 2; size <= n; size <<= 1) {
        for (int stride = size >> 1; stride > 0; stride >>= 1) {
            __syncthreads();
            for (int i = tid; i < (n >> 1); i += nt) {
                int pos = 2 * i - (i & (stride - 1));
                bool up = ((pos & size) == 0);
                unsigned long long x = a[pos], y = a[pos + stride];
                if ((x > y) == up) { a[pos] = y; a[pos + stride] = x; }
            }
        }
    }
    __syncthreads();
}

__device__ __forceinline__ uint32_t smem_u32(const void* p) {
    uint32_t a;
    asm("{ .reg .u64 t; cvta.to.shared.u64 t, %1; cvt.u32.u64 %0, t; }" : "=r"(a) : "l"(p));
    return a;
}

// ---------------------------------------------------------------------------
// K0: zero masks, dest maps, psum, loss accumulators (graph replays).
// ---------------------------------------------------------------------------
__global__ void init_maps() {
    int g = blockIdx.x * blockDim.x + threadIdx.x;
    int stride = gridDim.x * blockDim.x;
    for (int i = g; i < 2 * PTOT / 32; i += stride) (&g_mask[0][0])[i] = 0u;
    unsigned* ms = (unsigned*)&g_msel[0][0];
    unsigned* ma = (unsigned*)&g_manc[0][0];
    for (int i = g; i < 2 * PTOT / 2; i += stride) { ms[i] = 0u; ma[i] = 0u; }
    float* ps = &g_psum[0][0][0];
    for (int i = g; i < 2 * NCLS * DIM; i += stride) ps[i] = 0.f;
    if (g == 0) { g_loss = 0.0; g_done = 0u; }
}

// ---------------------------------------------------------------------------
// K1: merged selection kernel.
// blocks 0..59: top-k pixel selection -> dest maps; 60..99: perms -> pinv;
// 100..139: bank sampling -> samp.
// ---------------------------------------------------------------------------
__global__ void __launch_bounds__(1024) sel3(
        const int* __restrict__ mgt, const int* __restrict__ agt,
        unsigned km0, unsigned km1, unsigned ke0, unsigned ke1,
        unsigned ka0, unsigned ka1,
        unsigned k2m0, unsigned k2m1, unsigned k2e0, unsigned k2e1,
        unsigned ksm0, unsigned ksm1, unsigned kse0, unsigned kse1) {
    int bid = blockIdx.x, tid = threadIdx.x;

    if (bid < 60) {
        int task = bid / NCLS, c = bid % NCLS;
        int N = (task == 2) ? 131072 : 65536;
        int k = (task == 2) ? MV : MEMB;
        unsigned K0 = (task == 0) ? km0 : (task == 1) ? ke0 : ka0;
        unsigned K1 = (task == 0) ? km1 : (task == 1) ? ke1 : ka1;

        __shared__ int hist[1024];
        __shared__ unsigned long long cand[2048];
        __shared__ int s_cnt, s_cut;

        hist[tid] = 0;
        __syncthreads();

        unsigned base = (unsigned)c * (unsigned)N;
        int iters = N >> 12;
        for (int it = 0; it < iters; it++) {
            int i0 = (it << 12) + (tid << 2);
            const int* src = (task == 0) ? mgt : (task == 1) ? agt
                           : (i0 < 65536 ? mgt : agt);
            int off = (task == 2 && i0 >= 65536) ? i0 - 65536 : i0;
            int4 l4 = *(const int4*)(src + off);
            int ls[4] = { l4.x, l4.y, l4.z, l4.w };
#pragma unroll
            for (int j = 0; j < 4; j++) {
                if (ls[j] == c) {
                    unsigned bits = tfx(K0, K1, base + (unsigned)(i0 + j));
                    atomicAdd(&hist[bits >> 22], 1);
                }
            }
        }
        __syncthreads();
        if (tid == 0) {
            int cum = 0, cut = 1023;
            for (int b = 0; b < 1024; b++) { cum += hist[b]; if (cum >= k) { cut = b; break; } }
            s_cut = cut; s_cnt = 0;
        }
        __syncthreads();
        unsigned cut = (unsigned)s_cut;
        for (int it = 0; it < iters; it++) {
            int i0 = (it << 12) + (tid << 2);
            const int* src = (task == 0) ? mgt : (task == 1) ? agt
                           : (i0 < 65536 ? mgt : agt);
            int off = (task == 2 && i0 >= 65536) ? i0 - 65536 : i0;
            int4 l4 = *(const int4*)(src + off);
            int ls[4] = { l4.x, l4.y, l4.z, l4.w };
#pragma unroll
            for (int j = 0; j < 4; j++) {
                if (ls[j] == c) {
                    unsigned bits = tfx(K0, K1, base + (unsigned)(i0 + j));
                    if ((bits >> 22) <= cut) {
                        int p = atomicAdd(&s_cnt, 1);
                        if (p < 2048)
                            cand[p] = ((unsigned long long)(bits >> 9) << 32) | (unsigned)(i0 + j);
                    }
                }
            }
        }
        __syncthreads();
        int cnt = min(s_cnt, 2048);
        for (int i = cnt + tid; i < 2048; i += 1024) cand[i] = 0xFFFFFFFFFFFFFFFFull;
        bitonic(cand, 2048, tid, 1024);

        for (int j = tid; j < k; j += 1024) {
            int idx = (int)(cand[j] & 0xFFFFFFFFu);
            if (task == 0) {
                g_msel[0][idx] = (unsigned short)(c * MEMB + j + 1);
                atomicOr(&g_mask[0][idx >> 5], 1u << (idx & 31));
            } else if (task == 1) {
                g_msel[1][idx] = (unsigned short)(c * MEMB + j + 1);
                atomicOr(&g_mask[1][idx >> 5], 1u << (idx & 31));
            } else {
                unsigned short a = (unsigned short)(c * MV + j + 1);
                if (idx < 65536) {
                    g_manc[0][idx] = a;
                    atomicOr(&g_mask[0][idx >> 5], 1u << (idx & 31));
                } else {
                    int p = idx - 65536;
                    g_manc[1][p] = a;
                    atomicOr(&g_mask[1][p >> 5], 1u << (p & 31));
                }
            }
        }
    } else if (bid < 100) {
        int q = bid - 60;
        int u = q / NCLS, c = q % NCLS;
        unsigned a0, a1, b0, b1;
        tf2x32(u ? k2e0 : k2m0, u ? k2e1 : k2m1, 0u, (unsigned)c, a0, a1);
        tf2x32(a0, a1, 0u, 1u, b0, b1);
        __shared__ unsigned long long arr[512];
        for (int j = tid; j < 512; j += 1024) {
            unsigned bits = tfx(b0, b1, (unsigned)j);
            arr[j] = ((unsigned long long)bits << 32) | (unsigned)j;
        }
        bitonic(arr, 512, tid, 1024);
        for (int j = tid; j < 512; j += 1024) {
            int slot = (int)(arr[j] & 0xFFFFFFFFu);
            g_pinv[u][c][slot] = j;
        }
    } else {
        int q = bid - 100;
        int u = q / NCLS, c = q % NCLS;
        unsigned K0 = u ? kse0 : ksm0, K1 = u ? kse1 : ksm1;
        __shared__ unsigned long long arr[512];
        for (int j = tid; j < 512; j += 1024) {
            unsigned bits = tfx(K0, K1, (unsigned)(c * 512 + j));
            arr[j] = ((unsigned long long)(bits >> 9) << 32) | (unsigned)j;
        }
        bitonic(arr, 512, tid, 1024);
        for (int j = tid; j < MV; j += 1024)
            g_samp[u][c][j] = (int)(arr[j] & 0xFFFFFFFFu);
    }
}

// ---------------------------------------------------------------------------
// K2: coalesced scan of both projections; scatter RAW selected values.
// ---------------------------------------------------------------------------
__global__ void scan_scatter(const float* __restrict__ mainp,
                             const float* __restrict__ auxp) {
    const int total = 2 * 4 * 256 * 4096;
    int g = blockIdx.x * blockDim.x + threadIdx.x;
    int stride = gridDim.x * blockDim.x;
    for (int i = g; i < total; i += stride) {
        int s4 = i & 4095;
        int c  = (i >> 12) & 255;
        int b  = (i >> 20) & 3;
        int m  = i >> 22;
        int s  = s4 << 2;
        int pix = (b << 14) + s;
        unsigned nib = (g_mask[m][pix >> 5] >> (pix & 31)) & 0xFu;
        if (!nib) continue;
        const float* src = m ? auxp : mainp;
        float4 v = *(const float4*)(src + (((size_t)(b * 256 + c)) << 14) + s);
        ushort4 sl = *(const ushort4*)&g_msel[m][pix];
        ushort4 an = *(const ushort4*)&g_manc[m][pix];
        float vv[4] = { v.x, v.y, v.z, v.w };
        unsigned short sls[4] = { sl.x, sl.y, sl.z, sl.w };
        unsigned short ans[4] = { an.x, an.y, an.z, an.w };
#pragma unroll
        for (int e = 0; e < 4; e++) {
            if ((nib >> e) & 1u) {
                if (sls[e]) g_selvec[m][sls[e] - 1][c] = vv[e];
                if (ans[e]) g_anch[ans[e] - 1][c] = vv[e];
            }
        }
    }
}

// ---------------------------------------------------------------------------
// K3: fused normalize-anchors + bank-update/contrast + psum atomics.
// blocks [0,640): anchors (warp per row).  blocks [640,1920): sampled bank
// rows: con = l2norm(m*old[slot] + (1-m)*l2norm(feat[pinv[slot]])), and
// atomicAdd into g_psum.
// ---------------------------------------------------------------------------
__global__ void fuse_upd(const float* __restrict__ mainb,
                         const float* __restrict__ emab) {
    int bid = blockIdx.x;
    int lane = threadIdx.x & 31;
    if (bid < 640) {
        int w = bid * 8 + (threadIdx.x >> 5);
        float* row = g_anch[w];
        __half* row16 = &g_A16[w * DIM];
        float v[8]; float ss = 0.f;
#pragma unroll
        for (int t = 0; t < 8; t++) {
            v[t] = row[lane + 32 * t];
            ss += v[t] * v[t];
        }
        ss = wred(ss);
        float inv = 1.f / fmaxf(sqrtf(ss), 1e-12f);
#pragma unroll
        for (int t = 0; t < 8; t++) {
            float x = v[t] * inv;
            row[lane + 32 * t] = x;
            row16[lane + 32 * t] = __float2half(x);
        }
    } else {
        int w = (bid - 640) * 8 + (threadIdx.x >> 5);
        int u = w / NANC, q = w % NANC;
        int c = q >> 8;
        int slot = g_samp[u][c][q & 255];
        int j = g_pinv[u][c][slot];
        float m  = u ? 0.999f : 0.9f;
        float om = u ? 0.001f : 0.1f;
        const float* oldrow = (u ? emab : mainb) + (size_t)(c * MEMB + slot) * DIM;
        const float* feat = g_selvec[u][c * MEMB + j];
        float f[8], o[8];
        float ssf = 0.f;
#pragma unroll
        for (int t = 0; t < 8; t++) {
            int d = lane + 32 * t;
            f[t] = feat[d]; o[t] = oldrow[d];
            ssf += f[t] * f[t];
        }
        ssf = wred(ssf);
        float invf = 1.f / fmaxf(sqrtf(ssf), 1e-12f);
        float x[8]; float ss = 0.f;
#pragma unroll
        for (int t = 0; t < 8; t++) {
            float y = m * o[t] + om * (f[t] * invf);
            x[t] = y; ss += y * y;
        }
        ss = wred(ss);
        float inv = 1.f / fmaxf(sqrtf(ss), 1e-12f);
        float* dst = g_con[u][q];
        __half* dst16 = &g_B16[u][q * DIM];
#pragma unroll
        for (int t = 0; t < 8; t++) {
            int d = lane + 32 * t;
            float y = x[t] * inv;
            dst[d] = y;
            dst16[d] = __float2half(y);
            atomicAdd(&g_psum[u][c][d], y);
        }
    }
}

// ---------------------------------------------------------------------------
// K4: mma.sync fp16 GEMM + fused exp-rowsum. NSTAGE=2, 2 CTAs/SM.
// ---------------------------------------------------------------------------
#define KC 64
#define ROWP 72
#define TILE_H (128 * ROWP)
#define NSTAGE 2
#define GEMM_SMEM (NSTAGE * 2 * TILE_H * 2)   // 73728 B

__device__ __forceinline__ void ldsm_x4(uint32_t addr, uint32_t* r) {
    asm volatile("ldmatrix.sync.aligned.m8n8.x4.shared.b16 {%0,%1,%2,%3}, [%4];"
                 : "=r"(r[0]), "=r"(r[1]), "=r"(r[2]), "=r"(r[3]) : "r"(addr));
}
__device__ __forceinline__ void ldsm_x2(uint32_t addr, uint32_t* r) {
    asm volatile("ldmatrix.sync.aligned.m8n8.x2.shared.b16 {%0,%1}, [%2];"
                 : "=r"(r[0]), "=r"(r[1]) : "r"(addr));
}
__device__ __forceinline__ void mma16816(float* c, const uint32_t* a, const uint32_t* b) {
    asm volatile(
        "mma.sync.aligned.m16n8k16.row.col.f32.f16.f16.f32 "
        "{%0,%1,%2,%3}, {%4,%5,%6,%7}, {%8,%9}, {%0,%1,%2,%3};"
        : "+f"(c[0]), "+f"(c[1]), "+f"(c[2]), "+f"(c[3])
        : "r"(a[0]), "r"(a[1]), "r"(a[2]), "r"(a[3]), "r"(b[0]), "r"(b[1]));
}

__device__ __forceinline__ void load_tile(uint32_t dbase, const __half* __restrict__ src,
                                          int gRowBase, int kc, int tid) {
#pragma unroll
    for (int r = 0; r < 4; r++) {
        int s = tid + r * 256;
        int row = s >> 3;
        int c16 = s & 7;
        const __half* g = src + (size_t)(gRowBase + row) * DIM + kc * KC + c16 * 8;
        uint32_t d = dbase + row * (ROWP * 2) + c16 * 16;
        asm volatile("cp.async.cg.shared.global [%0], [%1], 16;" :: "r"(d), "l"(g) : "memory");
    }
}

__global__ void __launch_bounds__(256, 2) gemm_mma() {
    extern __shared__ __half smh[];
    uint32_t sbase = smem_u32(smh);
    __shared__ float red[128][5];

    const int u = blockIdx.z;
    const int rowBase = blockIdx.y * 128;
    const int colBase = blockIdx.x * 128;
    int tid = threadIdx.x, w = tid >> 5, lane = tid & 31;
    int wm = w >> 2, wn = w & 3;

    uint32_t stA[NSTAGE], stB[NSTAGE];
#pragma unroll
    for (int s = 0; s < NSTAGE; s++) {
        stA[s] = sbase + (uint32_t)(s * 2 * TILE_H * 2);
        stB[s] = stA[s] + (uint32_t)(TILE_H * 2);
    }

    const __half* A = g_A16;
    const __half* B = g_B16[u];

    float c[4][4][4];
#pragma unroll
    for (int mt = 0; mt < 4; mt++)
#pragma unroll
        for (int nt = 0; nt < 4; nt++)
#pragma unroll
            for (int e = 0; e < 4; e++) c[mt][nt][e] = 0.f;

#pragma unroll
    for (int s = 0; s < NSTAGE; s++) {
        load_tile(stA[s], A, rowBase, s, tid);
        load_tile(stB[s], B, colBase, s, tid);
        asm volatile("cp.async.commit_group;" ::: "memory");
    }

    int aRow = wm * 64 + (lane & 15);
    int aColOff = ((lane >> 4) << 3);
    int bRow = wn * 32 + (lane & 7);
    int bColOff = (((lane >> 3) & 1) << 3);

    uint32_t a[2][4][4], b[2][4][2];

#pragma unroll
    for (int i = 0; i < 4; i++) {
        asm volatile("cp.async.wait_group %0;" :: "n"(NSTAGE - 1) : "memory");
        __syncthreads();
        const int st = i % NSTAGE;

#pragma unroll
        for (int mt = 0; mt < 4; mt++)
            ldsm_x4(stA[st] + (uint32_t)((aRow + mt * 16) * (ROWP * 2) + aColOff * 2), a[0][mt]);
#pragma unroll
        for (int nt = 0; nt < 4; nt++)
            ldsm_x2(stB[st] + (uint32_t)((bRow + nt * 8) * (ROWP * 2) + bColOff * 2), b[0][nt]);

#pragma unroll
        for (int kk = 0; kk < 4; kk++) {
            const int cur = kk & 1, nxt = cur ^ 1;
            if (kk < 3) {
#pragma unroll
                for (int mt = 0; mt < 4; mt++)
                    ldsm_x4(stA[st] + (uint32_t)((aRow + mt * 16) * (ROWP * 2)
                          + ((kk + 1) * 16 + aColOff) * 2), a[nxt][mt]);
#pragma unroll
                for (int nt = 0; nt < 4; nt++)
                    ldsm_x2(stB[st] + (uint32_t)((bRow + nt * 8) * (ROWP * 2)
                          + ((kk + 1) * 16 + bColOff) * 2), b[nxt][nt]);
            }
#pragma unroll
            for (int mt = 0; mt < 4; mt++)
#pragma unroll
                for (int nt = 0; nt < 4; nt++)
                    mma16816(c[mt][nt], a[cur][mt], b[cur][nt]);
        }
        __syncthreads();
        if (i + NSTAGE < 4) {
            load_tile(stA[st], A, rowBase, i + NSTAGE, tid);
            load_tile(stB[st], B, colBase, i + NSTAGE, tid);
        }
        asm volatile("cp.async.commit_group;" ::: "memory");
    }

#pragma unroll
    for (int mt = 0; mt < 4; mt++) {
        float s0 = 0.f, s1 = 0.f;
#pragma unroll
        for (int nt = 0; nt < 4; nt++) {
            s0 += __expf(10.f * c[mt][nt][0]) + __expf(10.f * c[mt][nt][1]);
            s1 += __expf(10.f * c[mt][nt][2]) + __expf(10.f * c[mt][nt][3]);
        }
        s0 += __shfl_xor_sync(0xffffffffu, s0, 1);
        s0 += __shfl_xor_sync(0xffffffffu, s0, 2);
        s1 += __shfl_xor_sync(0xffffffffu, s1, 1);
        s1 += __shfl_xor_sync(0xffffffffu, s1, 2);
        if ((lane & 3) == 0) {
            int r0 = wm * 64 + mt * 16 + (lane >> 2);
            red[r0][wn] = s0;
            red[r0 + 8][wn] = s1;
        }
    }
    __syncthreads();
    if (tid < 128) {
        float s = red[tid][0] + red[tid][1] + red[tid][2] + red[tid][3];
        g_part[u][blockIdx.x][rowBase + tid] = s;
    }
}

// ---------------------------------------------------------------------------
// K5: fused plp + loss. Warp per anchor; double atomicAdd into g_loss;
// last block writes the output scalar.
// ---------------------------------------------------------------------------
__global__ void plp_loss(float* out) {
    __shared__ bool isLast;
    int w = blockIdx.x * 8 + (threadIdx.x >> 5);
    int lane = threadIdx.x & 31;
    int u = w / NANC, i = w % NANC;
    int c = i >> 8;
    float pd = 0.f;
#pragma unroll
    for (int t = 0; t < 8; t++) {
        int d = lane + 32 * t;
        pd += g_anch[i][d] * g_psum[u][c][d];
    }
    pd = wred(pd);
    float s = 0.f;
    for (int t = lane; t < NTIL; t += 32) s += g_part[u][t][i];
    s = wred(s);
    if (lane == 0) {
        float plp = pd * (10.f / 256.f) - logf(s);
        atomicAdd(&g_loss, (double)plp);
    }
    __syncthreads();
    if (threadIdx.x == 0) {
        __threadfence();
        unsigned old = atomicAdd(&g_done, 1u);
        isLast = (old == gridDim.x - 1);
    }
    __syncthreads();
    if (isLast && threadIdx.x == 0) {
        __threadfence();
        double v = *((volatile double*)&g_loss);
        out[0] = (float)(-v / 10240.0);
    }
}

// ---------------------------------------------------------------------------
extern "C" void kernel_launch(void* const* d_in, const int* in_sizes, int n_in,
                              void* d_out, int out_size) {
    (void)in_sizes; (void)n_in; (void)out_size;
    const float* main_proj = (const float*)d_in[0];
    const int*   main_gt   = (const int*)d_in[1];
    const float* aux_proj  = (const float*)d_in[2];
    const int*   aux_gt    = (const int*)d_in[3];
    const float* ema_bank  = (const float*)d_in[4];
    const float* main_bank = (const float*)d_in[5];
    float* out = (float*)d_out;

    unsigned ks[5][2];
    for (unsigned j = 0; j < 5; j++) tf2x32(0u, 42u, 0u, j, ks[j][0], ks[j][1]);
    unsigned k1m[2], k2m[2], k1e[2], k2e[2];
    tf2x32(ks[0][0], ks[0][1], 0u, 0u, k1m[0], k1m[1]);
    tf2x32(ks[0][0], ks[0][1], 0u, 1u, k2m[0], k2m[1]);
    tf2x32(ks[1][0], ks[1][1], 0u, 0u, k1e[0], k1e[1]);
    tf2x32(ks[1][0], ks[1][1], 0u, 1u, k2e[0], k2e[1]);

    cudaFuncSetAttribute(gemm_mma, cudaFuncAttributeMaxDynamicSharedMemorySize, GEMM_SMEM);

    init_maps<<<132, 256>>>();
    sel3<<<140, 1024>>>(main_gt, aux_gt,
                        k1m[0], k1m[1], k1e[0], k1e[1], ks[2][0], ks[2][1],
                        k2m[0], k2m[1], k2e[0], k2e[1],
                        ks[4][0], ks[4][1], ks[3][0], ks[3][1]);
    scan_scatter<<<4096, 256>>>(main_proj, aux_proj);
    fuse_upd<<<1920, 256>>>(main_bank, ema_bank);
    gemm_mma<<<dim3(NTIL, NTIL, 2), 256, GEMM_SMEM>>>();
    plp_loss<<<1280, 256>>>(out);
}

// round 16
// speedup vs baseline: 1.0189x; 1.0189x over previous
#include <cuda_runtime.h>
#include <cuda_fp16.h>
#include <cstdint>
#include <stdint.h>
#include <math.h>

// ---------------------------------------------------------------------------
// MemoryBankContrastLoss — JAX-threefry-exact pipeline, mma.sync (HMMA) GEMM.
// u==0 -> main, u==1 -> ema.  5-launch self-cleaning pipeline:
//   sel3 (zeroes psum) -> scan_scatter -> fuse_upd (+map cleanup)
//   -> gemm_mma (profiled slot) -> plp_loss (resets loss/done)
// Device globals are zero-initialized at module load, and every kernel
// restores the zero-invariant it relies on, so graph replays are exact.
// ---------------------------------------------------------------------------

#define NCLS 20
#define MEMB 512
#define MV   256
#define DIM  256
#define NANC 5120    // 20*256 anchors
#define NSEL 10240   // 20*512 selections per modality
#define PTOT 65536   // pixels per modality
#define NTIL 40      // 5120/128 col tiles per GEMM dimension

// ------------------------------ scratch ------------------------------------
__device__ unsigned       g_mask[2][PTOT / 32];
__device__ unsigned short g_msel[2][PTOT];
__device__ unsigned short g_manc[2][PTOT];
__device__ int    g_pinv  [2][NCLS][MEMB];
__device__ int    g_samp  [2][NCLS][MV];
__device__ float  g_selvec[2][NSEL][DIM];
__device__ float  g_anch  [NANC][DIM];
__device__ float  g_con   [2][NANC][DIM];
__device__ float  g_psum  [2][NCLS][DIM];
__device__ float  g_part  [2][NTIL][NANC];
__device__ double g_loss;
__device__ unsigned g_done;

// fp16 copies for the tensor-core GEMM
__device__ __align__(16) __half g_A16[NANC*DIM];
__device__ __align__(16) __half g_B16[2][NANC*DIM];

// ------------------------------ threefry -----------------------------------
__host__ __device__ __forceinline__ void tf2x32(unsigned k0, unsigned k1,
                                                unsigned c0, unsigned c1,
                                                unsigned& o0, unsigned& o1) {
    unsigned ks0 = k0, ks1 = k1, ks2 = k0 ^ k1 ^ 0x1BD11BDAu;
    unsigned x0 = c0 + ks0, x1 = c1 + ks1;
#define TFRND(r) { x0 += x1; x1 = (x1 << r) | (x1 >> (32 - r)); x1 ^= x0; }
    TFRND(13) TFRND(15) TFRND(26) TFRND(6)   x0 += ks1; x1 += ks2 + 1u;
    TFRND(17) TFRND(29) TFRND(16) TFRND(24)  x0 += ks2; x1 += ks0 + 2u;
    TFRND(13) TFRND(15) TFRND(26) TFRND(6)   x0 += ks0; x1 += ks1 + 3u;
    TFRND(17) TFRND(29) TFRND(16) TFRND(24)  x0 += ks1; x1 += ks2 + 4u;
    TFRND(13) TFRND(15) TFRND(26) TFRND(6)   x0 += ks2; x1 += ks0 + 5u;
#undef TFRND
    o0 = x0; o1 = x1;
}

__host__ __device__ __forceinline__ unsigned tfx(unsigned k0, unsigned k1, unsigned ctr) {
    unsigned a, b;
    tf2x32(k0, k1, 0u, ctr, a, b);
    return a ^ b;
}

// ------------------------------ helpers ------------------------------------
__device__ __forceinline__ float wred(float v) {
#pragma unroll
    for (int o = 16; o > 0; o >>= 1) v += __shfl_xor_sync(0xffffffffu, v, o);
    return v;
}

__device__ __forceinline__ void bitonic(unsigned long long* a, int n, int tid, int nt) {
    for (int size = 2; size <= n; size <<= 1) {
        for (int stride = size >> 1; stride > 0; stride >>= 1) {
            __syncthreads();
            for (int i = tid; i < (n >> 1); i += nt) {
                int pos = 2 * i - (i & (stride - 1));
                bool up = ((pos & size) == 0);
                unsigned long long x = a[pos], y = a[pos + stride];
                if ((x > y) == up) { a[pos] = y; a[pos + stride] = x; }
            }
        }
    }
    __syncthreads();
}

__device__ __forceinline__ uint32_t smem_u32(const void* p) {
    uint32_t a;
    asm("{ .reg .u64 t; cvta.to.shared.u64 t, %1; cvt.u32.u64 %0, t; }" : "=r"(a) : "l"(p));
    return a;
}

// ---------------------------------------------------------------------------
// K1: merged selection kernel.
// blocks 0..59: top-k pixel selection -> dest maps; 60..99: perms -> pinv;
// 100..139: bank sampling -> samp (+ zero g_psum for this replay).
// ---------------------------------------------------------------------------
__global__ void __launch_bounds__(1024) sel3(
        const int* __restrict__ mgt, const int* __restrict__ agt,
        unsigned km0, unsigned km1, unsigned ke0, unsigned ke1,
        unsigned ka0, unsigned ka1,
        unsigned k2m0, unsigned k2m1, unsigned k2e0, unsigned k2e1,
        unsigned ksm0, unsigned ksm1, unsigned kse0, unsigned kse1) {
    int bid = blockIdx.x, tid = threadIdx.x;

    if (bid < 60) {
        int task = bid / NCLS, c = bid % NCLS;
        int N = (task == 2) ? 131072 : 65536;
        int k = (task == 2) ? MV : MEMB;
        unsigned K0 = (task == 0) ? km0 : (task == 1) ? ke0 : ka0;
        unsigned K1 = (task == 0) ? km1 : (task == 1) ? ke1 : ka1;

        __shared__ int hist[1024];
        __shared__ unsigned long long cand[2048];
        __shared__ int s_cnt, s_cut;

        hist[tid] = 0;
        __syncthreads();

        unsigned base = (unsigned)c * (unsigned)N;
        int iters = N >> 12;
        for (int it = 0; it < iters; it++) {
            int i0 = (it << 12) + (tid << 2);
            const int* src = (task == 0) ? mgt : (task == 1) ? agt
                           : (i0 < 65536 ? mgt : agt);
            int off = (task == 2 && i0 >= 65536) ? i0 - 65536 : i0;
            int4 l4 = *(const int4*)(src + off);
            int ls[4] = { l4.x, l4.y, l4.z, l4.w };
#pragma unroll
            for (int j = 0; j < 4; j++) {
                if (ls[j] == c) {
                    unsigned bits = tfx(K0, K1, base + (unsigned)(i0 + j));
                    atomicAdd(&hist[bits >> 22], 1);
                }
            }
        }
        __syncthreads();
        if (tid == 0) {
            int cum = 0, cut = 1023;
            for (int b = 0; b < 1024; b++) { cum += hist[b]; if (cum >= k) { cut = b; break; } }
            s_cut = cut; s_cnt = 0;
        }
        __syncthreads();
        unsigned cut = (unsigned)s_cut;
        for (int it = 0; it < iters; it++) {
            int i0 = (it << 12) + (tid << 2);
            const int* src = (task == 0) ? mgt : (task == 1) ? agt
                           : (i0 < 65536 ? mgt : agt);
            int off = (task == 2 && i0 >= 65536) ? i0 - 65536 : i0;
            int4 l4 = *(const int4*)(src + off);
            int ls[4] = { l4.x, l4.y, l4.z, l4.w };
#pragma unroll
            for (int j = 0; j < 4; j++) {
                if (ls[j] == c) {
                    unsigned bits = tfx(K0, K1, base + (unsigned)(i0 + j));
                    if ((bits >> 22) <= cut) {
                        int p = atomicAdd(&s_cnt, 1);
                        if (p < 2048)
                            cand[p] = ((unsigned long long)(bits >> 9) << 32) | (unsigned)(i0 + j);
                    }
                }
            }
        }
        __syncthreads();
        int cnt = min(s_cnt, 2048);
        for (int i = cnt + tid; i < 2048; i += 1024) cand[i] = 0xFFFFFFFFFFFFFFFFull;
        bitonic(cand, 2048, tid, 1024);

        for (int j = tid; j < k; j += 1024) {
            int idx = (int)(cand[j] & 0xFFFFFFFFu);
            if (task == 0) {
                g_msel[0][idx] = (unsigned short)(c * MEMB + j + 1);
                atomicOr(&g_mask[0][idx >> 5], 1u << (idx & 31));
            } else if (task == 1) {
                g_msel[1][idx] = (unsigned short)(c * MEMB + j + 1);
                atomicOr(&g_mask[1][idx >> 5], 1u << (idx & 31));
            } else {
                unsigned short a = (unsigned short)(c * MV + j + 1);
                if (idx < 65536) {
                    g_manc[0][idx] = a;
                    atomicOr(&g_mask[0][idx >> 5], 1u << (idx & 31));
                } else {
                    int p = idx - 65536;
                    g_manc[1][p] = a;
                    atomicOr(&g_mask[1][p >> 5], 1u << (p & 31));
                }
            }
        }
    } else if (bid < 100) {
        int q = bid - 60;
        int u = q / NCLS, c = q % NCLS;
        unsigned a0, a1, b0, b1;
        tf2x32(u ? k2e0 : k2m0, u ? k2e1 : k2m1, 0u, (unsigned)c, a0, a1);
        tf2x32(a0, a1, 0u, 1u, b0, b1);
        __shared__ unsigned long long arr[512];
        for (int j = tid; j < 512; j += 1024) {
            unsigned bits = tfx(b0, b1, (unsigned)j);
            arr[j] = ((unsigned long long)bits << 32) | (unsigned)j;
        }
        bitonic(arr, 512, tid, 1024);
        for (int j = tid; j < 512; j += 1024) {
            int slot = (int)(arr[j] & 0xFFFFFFFFu);
            g_pinv[u][c][slot] = j;
        }
    } else {
        // zero psum for this replay (reader plp_loss of the PREVIOUS replay
        // has completed; writer fuse_upd of THIS replay has not started)
        {
            float* ps = &g_psum[0][0][0];
            int i = (bid - 100) * 1024 + tid;
            if (i < 2 * NCLS * DIM) ps[i] = 0.f;
        }
        int q = bid - 100;
        int u = q / NCLS, c = q % NCLS;
        unsigned K0 = u ? kse0 : ksm0, K1 = u ? kse1 : ksm1;
        __shared__ unsigned long long arr[512];
        for (int j = tid; j < 512; j += 1024) {
            unsigned bits = tfx(K0, K1, (unsigned)(c * 512 + j));
            arr[j] = ((unsigned long long)(bits >> 9) << 32) | (unsigned)j;
        }
        bitonic(arr, 512, tid, 1024);
        for (int j = tid; j < MV; j += 1024)
            g_samp[u][c][j] = (int)(arr[j] & 0xFFFFFFFFu);
    }
}

// ---------------------------------------------------------------------------
// K2: coalesced scan of both projections; scatter RAW selected values.
// ---------------------------------------------------------------------------
__global__ void scan_scatter(const float* __restrict__ mainp,
                             const float* __restrict__ auxp) {
    const int total = 2 * 4 * 256 * 4096;
    int g = blockIdx.x * blockDim.x + threadIdx.x;
    int stride = gridDim.x * blockDim.x;
    for (int i = g; i < total; i += stride) {
        int s4 = i & 4095;
        int c  = (i >> 12) & 255;
        int b  = (i >> 20) & 3;
        int m  = i >> 22;
        int s  = s4 << 2;
        int pix = (b << 14) + s;
        unsigned nib = (g_mask[m][pix >> 5] >> (pix & 31)) & 0xFu;
        if (!nib) continue;
        const float* src = m ? auxp : mainp;
        float4 v = *(const float4*)(src + (((size_t)(b * 256 + c)) << 14) + s);
        ushort4 sl = *(const ushort4*)&g_msel[m][pix];
        ushort4 an = *(const ushort4*)&g_manc[m][pix];
        float vv[4] = { v.x, v.y, v.z, v.w };
        unsigned short sls[4] = { sl.x, sl.y, sl.z, sl.w };
        unsigned short ans[4] = { an.x, an.y, an.z, an.w };
#pragma unroll
        for (int e = 0; e < 4; e++) {
            if ((nib >> e) & 1u) {
                if (sls[e]) g_selvec[m][sls[e] - 1][c] = vv[e];
                if (ans[e]) g_anch[ans[e] - 1][c] = vv[e];
            }
        }
    }
}

// ---------------------------------------------------------------------------
// K3: fused normalize-anchors + bank-update/contrast + psum atomics,
// plus map cleanup blocks (zero mask/msel/manc for the next replay — all
// readers of those maps finished in scan_scatter, the previous launch).
// blocks [0,640): anchors.  [640,1920): sampled bank rows.  [1920,1984): cleanup.
// ---------------------------------------------------------------------------
__global__ void fuse_upd(const float* __restrict__ mainb,
                         const float* __restrict__ emab) {
    int bid = blockIdx.x;
    int lane = threadIdx.x & 31;
    if (bid >= 1920) {
        int g = (bid - 1920) * 256 + threadIdx.x;     // 16384 threads
        int stride = 64 * 256;
        for (int i = g; i < 2 * PTOT / 32; i += stride) (&g_mask[0][0])[i] = 0u;
        unsigned* ms = (unsigned*)&g_msel[0][0];
        unsigned* ma = (unsigned*)&g_manc[0][0];
        for (int i = g; i < 2 * PTOT / 2; i += stride) { ms[i] = 0u; ma[i] = 0u; }
        return;
    }
    if (bid < 640) {
        int w = bid * 8 + (threadIdx.x >> 5);
        float* row = g_anch[w];
        __half* row16 = &g_A16[w * DIM];
        float v[8]; float ss = 0.f;
#pragma unroll
        for (int t = 0; t < 8; t++) {
            v[t] = row[lane + 32 * t];
            ss += v[t] * v[t];
        }
        ss = wred(ss);
        float inv = 1.f / fmaxf(sqrtf(ss), 1e-12f);
#pragma unroll
        for (int t = 0; t < 8; t++) {
            float x = v[t] * inv;
            row[lane + 32 * t] = x;
            row16[lane + 32 * t] = __float2half(x);
        }
    } else {
        int w = (bid - 640) * 8 + (threadIdx.x >> 5);
        int u = w / NANC, q = w % NANC;
        int c = q >> 8;
        int slot = g_samp[u][c][q & 255];
        int j = g_pinv[u][c][slot];
        float m  = u ? 0.999f : 0.9f;
        float om = u ? 0.001f : 0.1f;
        const float* oldrow = (u ? emab : mainb) + (size_t)(c * MEMB + slot) * DIM;
        const float* feat = g_selvec[u][c * MEMB + j];
        float f[8], o[8];
        float ssf = 0.f;
#pragma unroll
        for (int t = 0; t < 8; t++) {
            int d = lane + 32 * t;
            f[t] = feat[d]; o[t] = oldrow[d];
            ssf += f[t] * f[t];
        }
        ssf = wred(ssf);
        float invf = 1.f / fmaxf(sqrtf(ssf), 1e-12f);
        float x[8]; float ss = 0.f;
#pragma unroll
        for (int t = 0; t < 8; t++) {
            float y = m * o[t] + om * (f[t] * invf);
            x[t] = y; ss += y * y;
        }
        ss = wred(ss);
        float inv = 1.f / fmaxf(sqrtf(ss), 1e-12f);
        float* dst = g_con[u][q];
        __half* dst16 = &g_B16[u][q * DIM];
#pragma unroll
        for (int t = 0; t < 8; t++) {
            int d = lane + 32 * t;
            float y = x[t] * inv;
            dst[d] = y;
            dst16[d] = __float2half(y);
            atomicAdd(&g_psum[u][c][d], y);
        }
    }
}

// ---------------------------------------------------------------------------
// K4 (PROFILED SLOT): mma.sync fp16 GEMM + fused exp-rowsum.
// 128x128 CTA tile, 8 warps (2m x 4n), NSTAGE=3 cp.async ring + fragment
// double buffering (best measured config, from R10/R11).
// ---------------------------------------------------------------------------
#define KC 64
#define ROWP 72
#define TILE_H (128 * ROWP)
#define NSTAGE 3
#define GEMM_SMEM (NSTAGE * 2 * TILE_H * 2)   // 110592 B

__device__ __forceinline__ void ldsm_x4(uint32_t addr, uint32_t* r) {
    asm volatile("ldmatrix.sync.aligned.m8n8.x4.shared.b16 {%0,%1,%2,%3}, [%4];"
                 : "=r"(r[0]), "=r"(r[1]), "=r"(r[2]), "=r"(r[3]) : "r"(addr));
}
__device__ __forceinline__ void ldsm_x2(uint32_t addr, uint32_t* r) {
    asm volatile("ldmatrix.sync.aligned.m8n8.x2.shared.b16 {%0,%1}, [%2];"
                 : "=r"(r[0]), "=r"(r[1]) : "r"(addr));
}
__device__ __forceinline__ void mma16816(float* c, const uint32_t* a, const uint32_t* b) {
    asm volatile(
        "mma.sync.aligned.m16n8k16.row.col.f32.f16.f16.f32 "
        "{%0,%1,%2,%3}, {%4,%5,%6,%7}, {%8,%9}, {%0,%1,%2,%3};"
        : "+f"(c[0]), "+f"(c[1]), "+f"(c[2]), "+f"(c[3])
        : "r"(a[0]), "r"(a[1]), "r"(a[2]), "r"(a[3]), "r"(b[0]), "r"(b[1]));
}

__device__ __forceinline__ void load_tile(uint32_t dbase, const __half* __restrict__ src,
                                          int gRowBase, int kc, int tid) {
#pragma unroll
    for (int r = 0; r < 4; r++) {
        int s = tid + r * 256;
        int row = s >> 3;
        int c16 = s & 7;
        const __half* g = src + (size_t)(gRowBase + row) * DIM + kc * KC + c16 * 8;
        uint32_t d = dbase + row * (ROWP * 2) + c16 * 16;
        asm volatile("cp.async.cg.shared.global [%0], [%1], 16;" :: "r"(d), "l"(g) : "memory");
    }
}

__global__ void __launch_bounds__(256) gemm_mma() {
    extern __shared__ __half smh[];
    uint32_t sbase = smem_u32(smh);
    __shared__ float red[128][5];

    const int u = blockIdx.z;
    const int rowBase = blockIdx.y * 128;
    const int colBase = blockIdx.x * 128;
    int tid = threadIdx.x, w = tid >> 5, lane = tid & 31;
    int wm = w >> 2, wn = w & 3;

    uint32_t stA[NSTAGE], stB[NSTAGE];
#pragma unroll
    for (int s = 0; s < NSTAGE; s++) {
        stA[s] = sbase + (uint32_t)(s * 2 * TILE_H * 2);
        stB[s] = stA[s] + (uint32_t)(TILE_H * 2);
    }

    const __half* A = g_A16;
    const __half* B = g_B16[u];

    float c[4][4][4];
#pragma unroll
    for (int mt = 0; mt < 4; mt++)
#pragma unroll
        for (int nt = 0; nt < 4; nt++)
#pragma unroll
            for (int e = 0; e < 4; e++) c[mt][nt][e] = 0.f;

#pragma unroll
    for (int s = 0; s < NSTAGE; s++) {
        load_tile(stA[s], A, rowBase, s, tid);
        load_tile(stB[s], B, colBase, s, tid);
        asm volatile("cp.async.commit_group;" ::: "memory");
    }

    int aRow = wm * 64 + (lane & 15);
    int aColOff = ((lane >> 4) << 3);
    int bRow = wn * 32 + (lane & 7);
    int bColOff = (((lane >> 3) & 1) << 3);

    uint32_t a[2][4][4], b[2][4][2];

#pragma unroll
    for (int i = 0; i < 4; i++) {
        asm volatile("cp.async.wait_group %0;" :: "n"(NSTAGE - 1) : "memory");
        __syncthreads();
        const int st = i % NSTAGE;

#pragma unroll
        for (int mt = 0; mt < 4; mt++)
            ldsm_x4(stA[st] + (uint32_t)((aRow + mt * 16) * (ROWP * 2) + aColOff * 2), a[0][mt]);
#pragma unroll
        for (int nt = 0; nt < 4; nt++)
            ldsm_x2(stB[st] + (uint32_t)((bRow + nt * 8) * (ROWP * 2) + bColOff * 2), b[0][nt]);

#pragma unroll
        for (int kk = 0; kk < 4; kk++) {
            const int cur = kk & 1, nxt = cur ^ 1;
            if (kk < 3) {
#pragma unroll
                for (int mt = 0; mt < 4; mt++)
                    ldsm_x4(stA[st] + (uint32_t)((aRow + mt * 16) * (ROWP * 2)
                          + ((kk + 1) * 16 + aColOff) * 2), a[nxt][mt]);
#pragma unroll
                for (int nt = 0; nt < 4; nt++)
                    ldsm_x2(stB[st] + (uint32_t)((bRow + nt * 8) * (ROWP * 2)
                          + ((kk + 1) * 16 + bColOff) * 2), b[nxt][nt]);
            }
#pragma unroll
            for (int mt = 0; mt < 4; mt++)
#pragma unroll
                for (int nt = 0; nt < 4; nt++)
                    mma16816(c[mt][nt], a[cur][mt], b[cur][nt]);
        }
        __syncthreads();
        if (i + NSTAGE < 4) {
            load_tile(stA[st], A, rowBase, i + NSTAGE, tid);
            load_tile(stB[st], B, colBase, i + NSTAGE, tid);
        }
        asm volatile("cp.async.commit_group;" ::: "memory");
    }

#pragma unroll
    for (int mt = 0; mt < 4; mt++) {
        float s0 = 0.f, s1 = 0.f;
#pragma unroll
        for (int nt = 0; nt < 4; nt++) {
            s0 += __expf(10.f * c[mt][nt][0]) + __expf(10.f * c[mt][nt][1]);
            s1 += __expf(10.f * c[mt][nt][2]) + __expf(10.f * c[mt][nt][3]);
        }
        s0 += __shfl_xor_sync(0xffffffffu, s0, 1);
        s0 += __shfl_xor_sync(0xffffffffu, s0, 2);
        s1 += __shfl_xor_sync(0xffffffffu, s1, 1);
        s1 += __shfl_xor_sync(0xffffffffu, s1, 2);
        if ((lane & 3) == 0) {
            int r0 = wm * 64 + mt * 16 + (lane >> 2);
            red[r0][wn] = s0;
            red[r0 + 8][wn] = s1;
        }
    }
    __syncthreads();
    if (tid < 128) {
        float s = red[tid][0] + red[tid][1] + red[tid][2] + red[tid][3];
        g_part[u][blockIdx.x][rowBase + tid] = s;
    }
}

// ---------------------------------------------------------------------------
// K5: fused plp + loss; last block writes output and resets loss/done.
// ---------------------------------------------------------------------------
__global__ void plp_loss(float* out) {
    __shared__ bool isLast;
    int w = blockIdx.x * 8 + (threadIdx.x >> 5);
    int lane = threadIdx.x & 31;
    int u = w / NANC, i = w % NANC;
    int c = i >> 8;
    float pd = 0.f;
#pragma unroll
    for (int t = 0; t < 8; t++) {
        int d = lane + 32 * t;
        pd += g_anch[i][d] * g_psum[u][c][d];
    }
    pd = wred(pd);
    float s = 0.f;
    for (int t = lane; t < NTIL; t += 32) s += g_part[u][t][i];
    s = wred(s);
    if (lane == 0) {
        float plp = pd * (10.f / 256.f) - logf(s);
        atomicAdd(&g_loss, (double)plp);
    }
    __syncthreads();
    if (threadIdx.x == 0) {
        __threadfence();
        unsigned old = atomicAdd(&g_done, 1u);
        isLast = (old == gridDim.x - 1);
    }
    __syncthreads();
    if (isLast && threadIdx.x == 0) {
        __threadfence();
        double v = *((volatile double*)&g_loss);
        out[0] = (float)(-v / 10240.0);
        // reset accumulators for the next graph replay
        g_loss = 0.0;
        __threadfence();
        g_done = 0u;
    }
}

// ---------------------------------------------------------------------------
extern "C" void kernel_launch(void* const* d_in, const int* in_sizes, int n_in,
                              void* d_out, int out_size) {
    (void)in_sizes; (void)n_in; (void)out_size;
    const float* main_proj = (const float*)d_in[0];
    const int*   main_gt   = (const int*)d_in[1];
    const float* aux_proj  = (const float*)d_in[2];
    const int*   aux_gt    = (const int*)d_in[3];
    const float* ema_bank  = (const float*)d_in[4];
    const float* main_bank = (const float*)d_in[5];
    float* out = (float*)d_out;

    unsigned ks[5][2];
    for (unsigned j = 0; j < 5; j++) tf2x32(0u, 42u, 0u, j, ks[j][0], ks[j][1]);
    unsigned k1m[2], k2m[2], k1e[2], k2e[2];
    tf2x32(ks[0][0], ks[0][1], 0u, 0u, k1m[0], k1m[1]);
    tf2x32(ks[0][0], ks[0][1], 0u, 1u, k2m[0], k2m[1]);
    tf2x32(ks[1][0], ks[1][1], 0u, 0u, k1e[0], k1e[1]);
    tf2x32(ks[1][0], ks[1][1], 0u, 1u, k2e[0], k2e[1]);

    cudaFuncSetAttribute(gemm_mma, cudaFuncAttributeMaxDynamicSharedMemorySize, GEMM_SMEM);

    sel3<<<140, 1024>>>(main_gt, aux_gt,
                        k1m[0], k1m[1], k1e[0], k1e[1], ks[2][0], ks[2][1],
                        k2m[0], k2m[1], k2e[0], k2e[1],
                        ks[4][0], ks[4][1], ks[3][0], ks[3][1]);
    scan_scatter<<<4096, 256>>>(main_proj, aux_proj);
    fuse_upd<<<1984, 256>>>(main_bank, ema_bank);
    gemm_mma<<<dim3(NTIL, NTIL, 2), 256, GEMM_SMEM>>>();
    plp_loss<<<1280, 256>>>(out);
}